// round 1
// baseline (speedup 1.0000x reference)
#include <cuda_runtime.h>
#include <cuda_bf16.h>

// Problem dims
#define GB   4
#define GN_SEQ 4096
#define GH   16
#define GD   64
#define GC   1024
#define GM   16384          // GB*GN_SEQ
#define GK   1024
#define GNO  3072           // 3*GC

// GEMM tiling
#define BK   16
#define SROW 20             // padded smem row stride (conflict-free frag reads)
#define GEMM_SMEM (4 * 2 * 128 * SROW * 4)   // 81920 bytes

// ---------------- scratch (static device globals; no allocation) -------------
__device__ float g_qkv[(size_t)GM * GNO];        // 192 MB: qkv logits [16384][3072]
__device__ float g_cpart[64 * 4 * 64 * 64];      // per-(bh,chunk) unnormalized context
__device__ float g_spart[64 * 4 * 64];           // per-(bh,chunk) k-exp column sums
__device__ float g_ctx[64 * 64 * 64];            // normalized context [bh][d][e]

// ---------------- helpers ----------------------------------------------------
__device__ __forceinline__ void mma_tf32(float* d, const unsigned* a, const unsigned* b) {
    asm volatile(
        "mma.sync.aligned.m16n8k8.row.col.f32.tf32.tf32.f32 "
        "{%0,%1,%2,%3},{%4,%5,%6,%7},{%8,%9},{%0,%1,%2,%3};"
        : "+f"(d[0]), "+f"(d[1]), "+f"(d[2]), "+f"(d[3])
        : "r"(a[0]), "r"(a[1]), "r"(a[2]), "r"(a[3]), "r"(b[0]), "r"(b[1]));
}

__device__ __forceinline__ void split_store(float* hi, float* lo, int idx, float v) {
    unsigned hb;
    asm volatile("cvt.rna.tf32.f32 %0, %1;" : "=r"(hb) : "f"(v));
    float hf = __uint_as_float(hb);
    float res = v - hf;                 // exact (Dekker split)
    unsigned lb;
    asm volatile("cvt.rna.tf32.f32 %0, %1;" : "=r"(lb) : "f"(res));
    hi[idx] = hf;
    lo[idx] = __uint_as_float(lb);
}

// ---------------- Kernel 1: QKV GEMM (tf32 mma.sync, hi/lo split) -----------
// out[m][o] = sum_k A[m][k] * W[o][k].  Block tile 128x128, BK=16, double buffer.
__global__ __launch_bounds__(256) void qkv_gemm_kernel(const float* __restrict__ A,
                                                       const float* __restrict__ W)
{
    extern __shared__ float smem[];
    float* Ah = smem;
    float* Al = Ah + 2 * 128 * SROW;
    float* Wh = Al + 2 * 128 * SROW;
    float* Wl = Wh + 2 * 128 * SROW;

    const int t  = threadIdx.x;
    const int bm = blockIdx.x * 128;
    const int bn = blockIdx.y * 128;

    const int lane = t & 31;
    const int warp = t >> 5;
    const int wm = warp >> 2;        // 0..1  (64-row warp tiles)
    const int wn = warp & 3;         // 0..3  (32-col warp tiles)
    const int g  = lane >> 2;        // 0..7
    const int tc = lane & 3;         // 0..3

    // global-load mapping: 2 float4 per thread per matrix per tile
    const int lrow0 = t >> 2;        // 0..63
    const int lcol  = (t & 3) * 4;   // 0,4,8,12
    const float* Abase = A + (size_t)bm * GK;
    const float* Wbase = W + (size_t)bn * GK;

    float4 aReg0, aReg1, wReg0, wReg1;

#define LOADG(kt) do {                                                        \
    const float* ap = Abase + (size_t)lrow0 * GK + (size_t)(kt) * BK + lcol;  \
    aReg0 = *(const float4*)ap;                                               \
    aReg1 = *(const float4*)(ap + (size_t)64 * GK);                           \
    const float* wp = Wbase + (size_t)lrow0 * GK + (size_t)(kt) * BK + lcol;  \
    wReg0 = *(const float4*)wp;                                               \
    wReg1 = *(const float4*)(wp + (size_t)64 * GK);                           \
} while (0)

#define STORES(buf) do {                                                      \
    int b0 = ((buf) * 128 + lrow0) * SROW + lcol;                             \
    int b1 = ((buf) * 128 + lrow0 + 64) * SROW + lcol;                        \
    split_store(Ah, Al, b0 + 0, aReg0.x); split_store(Ah, Al, b0 + 1, aReg0.y);\
    split_store(Ah, Al, b0 + 2, aReg0.z); split_store(Ah, Al, b0 + 3, aReg0.w);\
    split_store(Ah, Al, b1 + 0, aReg1.x); split_store(Ah, Al, b1 + 1, aReg1.y);\
    split_store(Ah, Al, b1 + 2, aReg1.z); split_store(Ah, Al, b1 + 3, aReg1.w);\
    split_store(Wh, Wl, b0 + 0, wReg0.x); split_store(Wh, Wl, b0 + 1, wReg0.y);\
    split_store(Wh, Wl, b0 + 2, wReg0.z); split_store(Wh, Wl, b0 + 3, wReg0.w);\
    split_store(Wh, Wl, b1 + 0, wReg1.x); split_store(Wh, Wl, b1 + 1, wReg1.y);\
    split_store(Wh, Wl, b1 + 2, wReg1.z); split_store(Wh, Wl, b1 + 3, wReg1.w);\
} while (0)

    float acc[4][4][4];
#pragma unroll
    for (int i = 0; i < 4; ++i)
#pragma unroll
        for (int j = 0; j < 4; ++j)
#pragma unroll
            for (int c = 0; c < 4; ++c) acc[i][j][c] = 0.0f;

    LOADG(0);
    STORES(0);
    __syncthreads();

    const int NIT = GK / BK;   // 64
    for (int kt = 0; kt < NIT; ++kt) {
        int buf = kt & 1;
        if (kt + 1 < NIT) LOADG(kt + 1);

        const float* ah = Ah + buf * 128 * SROW;
        const float* al = Al + buf * 128 * SROW;
        const float* wh = Wh + buf * 128 * SROW;
        const float* wl = Wl + buf * 128 * SROW;

#pragma unroll
        for (int ks = 0; ks < 2; ++ks) {
            const int kb = ks * 8 + tc;
            unsigned afh[4][4], afl[4][4];
#pragma unroll
            for (int mt = 0; mt < 4; ++mt) {
                int rr = (wm * 64 + mt * 16 + g) * SROW;
                afh[mt][0] = __float_as_uint(ah[rr + kb]);
                afh[mt][1] = __float_as_uint(ah[rr + 8 * SROW + kb]);
                afh[mt][2] = __float_as_uint(ah[rr + kb + 4]);
                afh[mt][3] = __float_as_uint(ah[rr + 8 * SROW + kb + 4]);
                afl[mt][0] = __float_as_uint(al[rr + kb]);
                afl[mt][1] = __float_as_uint(al[rr + 8 * SROW + kb]);
                afl[mt][2] = __float_as_uint(al[rr + kb + 4]);
                afl[mt][3] = __float_as_uint(al[rr + 8 * SROW + kb + 4]);
            }
            unsigned bfh[4][2], bfl[4][2];
#pragma unroll
            for (int nt = 0; nt < 4; ++nt) {
                int rr = (wn * 32 + nt * 8 + g) * SROW;
                bfh[nt][0] = __float_as_uint(wh[rr + kb]);
                bfh[nt][1] = __float_as_uint(wh[rr + kb + 4]);
                bfl[nt][0] = __float_as_uint(wl[rr + kb]);
                bfl[nt][1] = __float_as_uint(wl[rr + kb + 4]);
            }
#pragma unroll
            for (int mt = 0; mt < 4; ++mt)
#pragma unroll
                for (int nt = 0; nt < 4; ++nt) {
                    mma_tf32(acc[mt][nt], afh[mt], bfh[nt]);  // hi*hi
                    mma_tf32(acc[mt][nt], afl[mt], bfh[nt]);  // lo*hi
                    mma_tf32(acc[mt][nt], afh[mt], bfl[nt]);  // hi*lo
                }
        }
        if (kt + 1 < NIT) { STORES(buf ^ 1); __syncthreads(); }
    }

    // epilogue: write qkv logits
#pragma unroll
    for (int mt = 0; mt < 4; ++mt)
#pragma unroll
        for (int nt = 0; nt < 4; ++nt) {
            int row = bm + wm * 64 + mt * 16 + g;
            int col = bn + wn * 32 + nt * 8 + tc * 2;
            *(float2*)(g_qkv + (size_t)row * GNO + col) =
                make_float2(acc[mt][nt][0], acc[mt][nt][1]);
            *(float2*)(g_qkv + (size_t)(row + 8) * GNO + col) =
                make_float2(acc[mt][nt][2], acc[mt][nt][3]);
        }
#undef LOADG
#undef STORES
}

// ---------------- Kernel 2: per-(bh,chunk) partial context + k-exp sums ------
// C[d][e] = sum_n exp(klogit[n][d]) * v[n][e];  S[d] = sum_n exp(klogit[n][d])
__global__ __launch_bounds__(512) void ctx_partial_kernel()
{
    const int bh    = blockIdx.x;   // 0..63
    const int chunk = blockIdx.y;   // 0..3 (1024 tokens each)
    const int b = bh >> 4, h = bh & 15;

    __shared__ __align__(16) float sk[32][64];
    __shared__ __align__(16) float sv[32][64];
    __shared__ __align__(16) float ps[32][64];

    const int t  = threadIdx.x;
    const int li = t >> 4;          // 0..31 (tile row for loads)
    const int lc = t & 15;          // 0..15 (float4 column)
    const int dg = t >> 4;          // d-group: d = dg*2 + {0,1}
    const int eg = t & 15;          // e-group: e = eg*4 + {0..3}

    float acc[2][4] = {{0, 0, 0, 0}, {0, 0, 0, 0}};
    float sacc[4] = {0, 0, 0, 0};

    const float* kbase = g_qkv + ((size_t)b * GN_SEQ) * GNO + 1024 + h * 64;

    for (int tile = 0; tile < 32; ++tile) {
        const int n = chunk * 1024 + tile * 32 + li;
        const float* kr = kbase + (size_t)n * GNO;
        float4 kk = *(const float4*)(kr + lc * 4);
        float4 vv = *(const float4*)(kr + 1024 + lc * 4);   // v = k + 1024 cols
        float4 ek;
        ek.x = __expf(kk.x); ek.y = __expf(kk.y);
        ek.z = __expf(kk.z); ek.w = __expf(kk.w);
        sacc[0] += ek.x; sacc[1] += ek.y; sacc[2] += ek.z; sacc[3] += ek.w;
        ((float4*)sk[li])[lc] = ek;
        ((float4*)sv[li])[lc] = vv;
        __syncthreads();
#pragma unroll 4
        for (int nn = 0; nn < 32; ++nn) {
            float a0 = sk[nn][dg * 2];
            float a1 = sk[nn][dg * 2 + 1];
            float4 v4 = ((float4*)sv[nn])[eg];
            acc[0][0] += a0 * v4.x; acc[0][1] += a0 * v4.y;
            acc[0][2] += a0 * v4.z; acc[0][3] += a0 * v4.w;
            acc[1][0] += a1 * v4.x; acc[1][1] += a1 * v4.y;
            acc[1][2] += a1 * v4.z; acc[1][3] += a1 * v4.w;
        }
        __syncthreads();
    }

    const size_t cbase = ((size_t)(bh * 4 + chunk)) * 4096;
#pragma unroll
    for (int i = 0; i < 2; ++i) {
        int d = dg * 2 + i;
        ((float4*)(g_cpart + cbase + d * 64))[eg] =
            make_float4(acc[i][0], acc[i][1], acc[i][2], acc[i][3]);
    }

    ((float4*)ps[li])[lc] = make_float4(sacc[0], sacc[1], sacc[2], sacc[3]);
    __syncthreads();
    if (t < 64) {
        float s = 0.0f;
#pragma unroll
        for (int i = 0; i < 32; ++i) s += ps[i][t];
        g_spart[(bh * 4 + chunk) * 64 + t] = s;   // deterministic fixed-order sum
    }
}

// ---------------- Kernel 3: reduce chunks + normalize context ---------------
__global__ __launch_bounds__(256) void ctx_reduce_kernel()
{
    const int bh = blockIdx.x;
    const int t  = threadIdx.x;
    __shared__ float sinvS[64];
    if (t < 64) {
        const float* sp = g_spart + (size_t)bh * 256 + t;
        float s = sp[0] + sp[64] + sp[128] + sp[192];
        sinvS[t] = 1.0f / s;
    }
    __syncthreads();
    const float* cp = g_cpart + (size_t)bh * 16384;
    for (int idx = t; idx < 4096; idx += 256) {
        float c = cp[idx] + cp[idx + 4096] + cp[idx + 8192] + cp[idx + 12288];
        g_ctx[(size_t)bh * 4096 + idx] = c * sinvS[idx >> 6];
    }
}

// ---------------- Kernel 4: q-softmax (over d) + out = q_soft @ ctx ---------
__global__ __launch_bounds__(256) void out_kernel_f(float* __restrict__ out)
{
    const int nb = blockIdx.x;   // 64-row block of tokens (64 blocks)
    const int bh = blockIdx.y;   // 0..63
    const int b = bh >> 4, h = bh & 15;

    __shared__ __align__(16) float sctx[64][64];
    __shared__ __align__(16) float sq[64][68];
    __shared__ float prow[64][4];
    __shared__ float sinv[64];

    const int t = threadIdx.x;

    // load normalized context
    const float4* cg = (const float4*)(g_ctx + (size_t)bh * 4096);
    float4* cs = (float4*)sctx;
#pragma unroll
    for (int j = 0; j < 4; ++j) cs[t + 256 * j] = cg[t + 256 * j];

    // q logits -> exp, row partial sums (4 threads per row)
    const int r  = t >> 2;
    const int qp = t & 3;
    const float* qrow = g_qkv + ((size_t)(b * GN_SEQ + nb * 64 + r)) * GNO + h * 64;
    float psum = 0.0f;
#pragma unroll
    for (int c4 = 0; c4 < 4; ++c4) {
        int d0 = qp * 16 + c4 * 4;
        float4 qv = *(const float4*)(qrow + d0);
        float e0 = __expf(qv.x), e1 = __expf(qv.y), e2 = __expf(qv.z), e3 = __expf(qv.w);
        sq[r][d0] = e0; sq[r][d0 + 1] = e1; sq[r][d0 + 2] = e2; sq[r][d0 + 3] = e3;
        psum += e0 + e1 + e2 + e3;
    }
    prow[r][qp] = psum;
    __syncthreads();
    if (t < 64)
        sinv[t] = 0.125f / (prow[t][0] + prow[t][1] + prow[t][2] + prow[t][3]);
    __syncthreads();

    // rescale exps in place (each thread its own 16 values)
    {
        float myinv = sinv[r];
#pragma unroll
        for (int c4 = 0; c4 < 4; ++c4) {
            int d0 = qp * 16 + c4 * 4;
            sq[r][d0] *= myinv; sq[r][d0 + 1] *= myinv;
            sq[r][d0 + 2] *= myinv; sq[r][d0 + 3] *= myinv;
        }
    }
    __syncthreads();

    // 64x64 @ 64x64: each thread 4 rows x 4 cols
    const int rg  = t >> 4;       // 0..15 -> rows rg*4 + i
    const int egx = t & 15;       // e quad
    float acc[4][4] = {{0}};
#pragma unroll 4
    for (int d = 0; d < 64; ++d) {
        float4 c4v = ((float4*)sctx[d])[egx];
#pragma unroll
        for (int i = 0; i < 4; ++i) {
            float qv = sq[rg * 4 + i][d];
            acc[i][0] += qv * c4v.x; acc[i][1] += qv * c4v.y;
            acc[i][2] += qv * c4v.z; acc[i][3] += qv * c4v.w;
        }
    }
#pragma unroll
    for (int i = 0; i < 4; ++i) {
        int n = nb * 64 + rg * 4 + i;
        ((float4*)(out + ((size_t)bh * GN_SEQ + n) * 64))[egx] =
            make_float4(acc[i][0], acc[i][1], acc[i][2], acc[i][3]);
    }
}

// ---------------- launcher ---------------------------------------------------
extern "C" void kernel_launch(void* const* d_in, const int* in_sizes, int n_in,
                              void* d_out, int out_size)
{
    const float* x = (const float*)d_in[0];     // [4,4096,1024]
    const float* w = (const float*)d_in[1];     // [3072,1024]
    float* out = (float*)d_out;                 // [4,16,4096,64]

    cudaFuncSetAttribute(qkv_gemm_kernel,
                         cudaFuncAttributeMaxDynamicSharedMemorySize, GEMM_SMEM);

    dim3 gGemm(GM / 128, GNO / 128);            // (128, 24)
    qkv_gemm_kernel<<<gGemm, 256, GEMM_SMEM>>>(x, w);

    dim3 gCtx(64, 4);
    ctx_partial_kernel<<<gCtx, 512>>>();

    ctx_reduce_kernel<<<64, 256>>>();

    dim3 gOut(64, 64);                          // (n-blocks, bh)
    out_kernel_f<<<gOut, 256>>>(out);
}

// round 2
// speedup vs baseline: 2.0212x; 2.0212x over previous
#include <cuda_runtime.h>
#include <cuda_bf16.h>

// Problem dims
#define GB     4
#define GN_SEQ 4096
#define GH     16
#define GD     64
#define GC     1024
#define GM     16384          // GB*GN_SEQ
#define GK     1024
#define GNO    3072           // 3*GC

// GEMM tiling
#define BM 128
#define BN 128
#define BKK 32
#define STAGES 4
#define STAGE_BYTES 16384              // 128 rows * 128B (hi 64B | lo 64B)
#define GEMM_SMEM (2 * STAGES * STAGE_BYTES)   // 128 KB

// ---------------- scratch (static device globals; no allocation) -------------
__device__ __nv_bfloat16 g_Ah[(size_t)GM * GK];
__device__ __nv_bfloat16 g_Al[(size_t)GM * GK];
__device__ __nv_bfloat16 g_Wh[(size_t)GNO * GK];
__device__ __nv_bfloat16 g_Wl[(size_t)GNO * GK];
__device__ float g_qkv[(size_t)GM * GNO];        // 192 MB qkv logits
__device__ float g_cpart[64 * 4 * 64 * 64];
__device__ float g_spart[64 * 4 * 64];
__device__ float g_ctx[64 * 64 * 64];

// ---------------- asm helpers ------------------------------------------------
#define LDSM4(r, addr)                                                         \
    asm volatile("ldmatrix.sync.aligned.m8n8.x4.shared.b16 {%0,%1,%2,%3},[%4];"\
                 : "=r"((r)[0]), "=r"((r)[1]), "=r"((r)[2]), "=r"((r)[3])      \
                 : "r"(addr))

#define MMA_BF16(d, a, b0, b1)                                                 \
    asm volatile("mma.sync.aligned.m16n8k16.row.col.f32.bf16.bf16.f32 "        \
                 "{%0,%1,%2,%3},{%4,%5,%6,%7},{%8,%9},{%0,%1,%2,%3};"          \
                 : "+f"((d)[0]), "+f"((d)[1]), "+f"((d)[2]), "+f"((d)[3])      \
                 : "r"((a)[0]), "r"((a)[1]), "r"((a)[2]), "r"((a)[3]),         \
                   "r"(b0), "r"(b1))

#define CP_ASYNC16(dst, src)                                                   \
    asm volatile("cp.async.cg.shared.global [%0],[%1],16;" ::                  \
                 "r"(dst), "l"(src) : "memory")

#define CP_COMMIT() asm volatile("cp.async.commit_group;" ::: "memory")
#define CP_WAIT2()  asm volatile("cp.async.wait_group 2;" ::: "memory")

// ---------------- Kernel 0: fp32 -> bf16 (hi,lo) split pre-pass --------------
__global__ __launch_bounds__(256) void split_kernel(const float* __restrict__ x,
                                                    const float* __restrict__ w)
{
    const size_t A4 = (size_t)GM * GK / 4;
    const size_t W4 = (size_t)GNO * GK / 4;
    const size_t total = A4 + W4;
    size_t stride = (size_t)gridDim.x * blockDim.x;
    for (size_t i = (size_t)blockIdx.x * blockDim.x + threadIdx.x; i < total; i += stride) {
        float4 v;
        if (i < A4) v = ((const float4*)x)[i];
        else        v = ((const float4*)w)[i - A4];
        __nv_bfloat16 h0 = __float2bfloat16(v.x);
        __nv_bfloat16 h1 = __float2bfloat16(v.y);
        __nv_bfloat16 h2 = __float2bfloat16(v.z);
        __nv_bfloat16 h3 = __float2bfloat16(v.w);
        __nv_bfloat16 l0 = __float2bfloat16(v.x - __bfloat162float(h0));
        __nv_bfloat16 l1 = __float2bfloat16(v.y - __bfloat162float(h1));
        __nv_bfloat16 l2 = __float2bfloat16(v.z - __bfloat162float(h2));
        __nv_bfloat16 l3 = __float2bfloat16(v.w - __bfloat162float(h3));
        __nv_bfloat162 hp0 = __halves2bfloat162(h0, h1);
        __nv_bfloat162 hp1 = __halves2bfloat162(h2, h3);
        __nv_bfloat162 lp0 = __halves2bfloat162(l0, l1);
        __nv_bfloat162 lp1 = __halves2bfloat162(l2, l3);
        if (i < A4) {
            ((__nv_bfloat162*)g_Ah)[i * 2]     = hp0;
            ((__nv_bfloat162*)g_Ah)[i * 2 + 1] = hp1;
            ((__nv_bfloat162*)g_Al)[i * 2]     = lp0;
            ((__nv_bfloat162*)g_Al)[i * 2 + 1] = lp1;
        } else {
            size_t j = i - A4;
            ((__nv_bfloat162*)g_Wh)[j * 2]     = hp0;
            ((__nv_bfloat162*)g_Wh)[j * 2 + 1] = hp1;
            ((__nv_bfloat162*)g_Wl)[j * 2]     = lp0;
            ((__nv_bfloat162*)g_Wl)[j * 2 + 1] = lp1;
        }
    }
}

// ---------------- Kernel 1: QKV GEMM (bf16 hi/lo, mma.sync, cp.async) -------
// smem row layout per stage: 128 rows x 128B; chunks 0-3 = hi 32 bf16, 4-7 = lo.
// swizzle: physical chunk = logical ^ (row & 7)  -> conflict-free LDSM & STS.
__device__ __forceinline__ void issue_stage(int kt, int bm, int bn,
                                            unsigned sA, unsigned sB, int t)
{
    const int k0 = kt * BKK;
    const unsigned bufA = sA + (kt & (STAGES - 1)) * STAGE_BYTES;
    const unsigned bufB = sB + (kt & (STAGES - 1)) * STAGE_BYTES;
#pragma unroll
    for (int i = 0; i < 4; ++i) {
        int idx = t + i * 256;
        int row = idx >> 3;
        int c   = idx & 7;
        unsigned soff = (unsigned)(row * 128 + ((c ^ (row & 7)) << 4));
        const __nv_bfloat16* ga = ((c < 4) ? g_Ah : g_Al) +
                                  (size_t)(bm + row) * GK + k0 + (c & 3) * 8;
        CP_ASYNC16(bufA + soff, ga);
        const __nv_bfloat16* gb = ((c < 4) ? g_Wh : g_Wl) +
                                  (size_t)(bn + row) * GK + k0 + (c & 3) * 8;
        CP_ASYNC16(bufB + soff, gb);
    }
}

__global__ __launch_bounds__(256, 1) void qkv_gemm_bf16()
{
    extern __shared__ char smraw[];
    const unsigned sbase = (unsigned)__cvta_generic_to_shared(smraw);
    const unsigned sA = sbase;
    const unsigned sB = sbase + STAGES * STAGE_BYTES;

    const int t    = threadIdx.x;
    const int bn   = blockIdx.x * BN;     // N fastest: W tile stays hot in L2
    const int bm   = blockIdx.y * BM;
    const int lane = t & 31;
    const int warp = t >> 5;
    const int wm   = warp >> 2;           // 0..1
    const int wn   = warp & 3;            // 0..3

    // per-lane ldmatrix offsets: off[hilo][ks]
    const int lr = lane & 15;
    const int ls = lane >> 4;
    unsigned off[2][2];
#pragma unroll
    for (int hl = 0; hl < 2; ++hl)
#pragma unroll
        for (int ks = 0; ks < 2; ++ks)
            off[hl][ks] = (unsigned)(lr * 128 +
                          (((hl << 2) + (ks << 1) + ls) ^ (lr & 7)) * 16);

    float acc[4][4][4];
#pragma unroll
    for (int i = 0; i < 4; ++i)
#pragma unroll
        for (int j = 0; j < 4; ++j)
#pragma unroll
            for (int c = 0; c < 4; ++c) acc[i][j][c] = 0.0f;

    // prologue: 3 stages in flight
    issue_stage(0, bm, bn, sA, sB, t); CP_COMMIT();
    issue_stage(1, bm, bn, sA, sB, t); CP_COMMIT();
    issue_stage(2, bm, bn, sA, sB, t); CP_COMMIT();

    const int NT = GK / BKK;   // 32
    for (int kt = 0; kt < NT; ++kt) {
        CP_WAIT2();
        __syncthreads();

        const unsigned aS = sA + (kt & (STAGES - 1)) * STAGE_BYTES + (wm * 64) * 128;
        const unsigned bS = sB + (kt & (STAGES - 1)) * STAGE_BYTES + (wn * 32) * 128;

#pragma unroll
        for (int ks = 0; ks < 2; ++ks) {
            unsigned ah[4][4], al[4][4];
#pragma unroll
            for (int mt = 0; mt < 4; ++mt) {
                LDSM4(ah[mt], aS + mt * 16 * 128 + off[0][ks]);
                LDSM4(al[mt], aS + mt * 16 * 128 + off[1][ks]);
            }
            unsigned bh[2][4], bl[2][4];
#pragma unroll
            for (int p = 0; p < 2; ++p) {
                LDSM4(bh[p], bS + p * 16 * 128 + off[0][ks]);
                LDSM4(bl[p], bS + p * 16 * 128 + off[1][ks]);
            }
#pragma unroll
            for (int mt = 0; mt < 4; ++mt)
#pragma unroll
                for (int p = 0; p < 2; ++p)
#pragma unroll
                    for (int j = 0; j < 2; ++j) {
                        const int nt = p * 2 + j;
                        MMA_BF16(acc[mt][nt], ah[mt], bh[p][j], bh[p][j + 2]);
                        MMA_BF16(acc[mt][nt], al[mt], bh[p][j], bh[p][j + 2]);
                        MMA_BF16(acc[mt][nt], ah[mt], bl[p][j], bl[p][j + 2]);
                    }
        }

        if (kt + STAGES - 1 < NT)
            issue_stage(kt + STAGES - 1, bm, bn, sA, sB, t);
        CP_COMMIT();   // empty group at tail keeps wait_group bookkeeping exact
    }

    // epilogue
    const int g  = lane >> 2;
    const int tc = lane & 3;
#pragma unroll
    for (int mt = 0; mt < 4; ++mt)
#pragma unroll
        for (int nt = 0; nt < 4; ++nt) {
            int row = bm + wm * 64 + mt * 16 + g;
            int col = bn + wn * 32 + nt * 8 + tc * 2;
            *(float2*)(g_qkv + (size_t)row * GNO + col) =
                make_float2(acc[mt][nt][0], acc[mt][nt][1]);
            *(float2*)(g_qkv + (size_t)(row + 8) * GNO + col) =
                make_float2(acc[mt][nt][2], acc[mt][nt][3]);
        }
}

// ---------------- Kernel 2: per-(bh,chunk) partial context + k-exp sums ------
__global__ __launch_bounds__(512) void ctx_partial_kernel()
{
    const int bh    = blockIdx.x;
    const int chunk = blockIdx.y;
    const int b = bh >> 4, h = bh & 15;

    __shared__ __align__(16) float sk[32][64];
    __shared__ __align__(16) float sv[32][64];
    __shared__ __align__(16) float ps[32][64];

    const int t  = threadIdx.x;
    const int li = t >> 4;
    const int lc = t & 15;
    const int dg = t >> 4;
    const int eg = t & 15;

    float acc[2][4] = {{0, 0, 0, 0}, {0, 0, 0, 0}};
    float sacc[4] = {0, 0, 0, 0};

    const float* kbase = g_qkv + ((size_t)b * GN_SEQ) * GNO + 1024 + h * 64;

    for (int tile = 0; tile < 32; ++tile) {
        const int n = chunk * 1024 + tile * 32 + li;
        const float* kr = kbase + (size_t)n * GNO;
        float4 kk = *(const float4*)(kr + lc * 4);
        float4 vv = *(const float4*)(kr + 1024 + lc * 4);
        float4 ek;
        ek.x = __expf(kk.x); ek.y = __expf(kk.y);
        ek.z = __expf(kk.z); ek.w = __expf(kk.w);
        sacc[0] += ek.x; sacc[1] += ek.y; sacc[2] += ek.z; sacc[3] += ek.w;
        ((float4*)sk[li])[lc] = ek;
        ((float4*)sv[li])[lc] = vv;
        __syncthreads();
#pragma unroll 4
        for (int nn = 0; nn < 32; ++nn) {
            float a0 = sk[nn][dg * 2];
            float a1 = sk[nn][dg * 2 + 1];
            float4 v4 = ((float4*)sv[nn])[eg];
            acc[0][0] += a0 * v4.x; acc[0][1] += a0 * v4.y;
            acc[0][2] += a0 * v4.z; acc[0][3] += a0 * v4.w;
            acc[1][0] += a1 * v4.x; acc[1][1] += a1 * v4.y;
            acc[1][2] += a1 * v4.z; acc[1][3] += a1 * v4.w;
        }
        __syncthreads();
    }

    const size_t cbase = ((size_t)(bh * 4 + chunk)) * 4096;
#pragma unroll
    for (int i = 0; i < 2; ++i) {
        int d = dg * 2 + i;
        ((float4*)(g_cpart + cbase + d * 64))[eg] =
            make_float4(acc[i][0], acc[i][1], acc[i][2], acc[i][3]);
    }

    ((float4*)ps[li])[lc] = make_float4(sacc[0], sacc[1], sacc[2], sacc[3]);
    __syncthreads();
    if (t < 64) {
        float s = 0.0f;
#pragma unroll
        for (int i = 0; i < 32; ++i) s += ps[i][t];
        g_spart[(bh * 4 + chunk) * 64 + t] = s;
    }
}

// ---------------- Kernel 3: reduce chunks + normalize context ---------------
__global__ __launch_bounds__(256) void ctx_reduce_kernel()
{
    const int bh = blockIdx.x;
    const int t  = threadIdx.x;
    __shared__ float sinvS[64];
    if (t < 64) {
        const float* sp = g_spart + (size_t)bh * 256 + t;
        float s = sp[0] + sp[64] + sp[128] + sp[192];
        sinvS[t] = 1.0f / s;
    }
    __syncthreads();
    const float* cp = g_cpart + (size_t)bh * 16384;
    for (int idx = t; idx < 4096; idx += 256) {
        float c = cp[idx] + cp[idx + 4096] + cp[idx + 8192] + cp[idx + 12288];
        g_ctx[(size_t)bh * 4096 + idx] = c * sinvS[idx >> 6];
    }
}

// ---------------- Kernel 4: q-softmax (over d) + out = q_soft @ ctx ---------
__global__ __launch_bounds__(256) void out_kernel_f(float* __restrict__ out)
{
    const int nb = blockIdx.x;
    const int bh = blockIdx.y;
    const int b = bh >> 4, h = bh & 15;

    __shared__ __align__(16) float sctx[64][64];
    __shared__ __align__(16) float sq[64][68];
    __shared__ float prow[64][4];
    __shared__ float sinv[64];

    const int t = threadIdx.x;

    const float4* cg = (const float4*)(g_ctx + (size_t)bh * 4096);
    float4* cs = (float4*)sctx;
#pragma unroll
    for (int j = 0; j < 4; ++j) cs[t + 256 * j] = cg[t + 256 * j];

    const int r  = t >> 2;
    const int qp = t & 3;
    const float* qrow = g_qkv + ((size_t)(b * GN_SEQ + nb * 64 + r)) * GNO + h * 64;
    float psum = 0.0f;
#pragma unroll
    for (int c4 = 0; c4 < 4; ++c4) {
        int d0 = qp * 16 + c4 * 4;
        float4 qv = *(const float4*)(qrow + d0);
        float e0 = __expf(qv.x), e1 = __expf(qv.y), e2 = __expf(qv.z), e3 = __expf(qv.w);
        sq[r][d0] = e0; sq[r][d0 + 1] = e1; sq[r][d0 + 2] = e2; sq[r][d0 + 3] = e3;
        psum += e0 + e1 + e2 + e3;
    }
    prow[r][qp] = psum;
    __syncthreads();
    if (t < 64)
        sinv[t] = 0.125f / (prow[t][0] + prow[t][1] + prow[t][2] + prow[t][3]);
    __syncthreads();

    {
        float myinv = sinv[r];
#pragma unroll
        for (int c4 = 0; c4 < 4; ++c4) {
            int d0 = qp * 16 + c4 * 4;
            sq[r][d0] *= myinv; sq[r][d0 + 1] *= myinv;
            sq[r][d0 + 2] *= myinv; sq[r][d0 + 3] *= myinv;
        }
    }
    __syncthreads();

    const int rg  = t >> 4;
    const int egx = t & 15;
    float acc[4][4] = {{0}};
#pragma unroll 4
    for (int d = 0; d < 64; ++d) {
        float4 c4v = ((float4*)sctx[d])[egx];
#pragma unroll
        for (int i = 0; i < 4; ++i) {
            float qv = sq[rg * 4 + i][d];
            acc[i][0] += qv * c4v.x; acc[i][1] += qv * c4v.y;
            acc[i][2] += qv * c4v.z; acc[i][3] += qv * c4v.w;
        }
    }
#pragma unroll
    for (int i = 0; i < 4; ++i) {
        int n = nb * 64 + rg * 4 + i;
        ((float4*)(out + ((size_t)bh * GN_SEQ + n) * 64))[egx] =
            make_float4(acc[i][0], acc[i][1], acc[i][2], acc[i][3]);
    }
}

// ---------------- launcher ----------------------------------------------------
extern "C" void kernel_launch(void* const* d_in, const int* in_sizes, int n_in,
                              void* d_out, int out_size)
{
    const float* x = (const float*)d_in[0];     // [4,4096,1024]
    const float* w = (const float*)d_in[1];     // [3072,1024]
    float* out = (float*)d_out;                 // [4,16,4096,64]

    cudaFuncSetAttribute(qkv_gemm_bf16,
                         cudaFuncAttributeMaxDynamicSharedMemorySize, GEMM_SMEM);

    split_kernel<<<4096, 256>>>(x, w);

    dim3 gGemm(GNO / BN, GM / BM);              // (24, 128) — N fastest for L2 reuse
    qkv_gemm_bf16<<<gGemm, 256, GEMM_SMEM>>>();

    dim3 gCtx(64, 4);
    ctx_partial_kernel<<<gCtx, 512>>>();

    ctx_reduce_kernel<<<64, 256>>>();

    dim3 gOut(64, 64);
    out_kernel_f<<<gOut, 256>>>(out);
}

// round 4
// speedup vs baseline: 3.0975x; 1.5325x over previous
#include <cuda_runtime.h>
#include <cuda_fp16.h>
#include <cstdint>

// Problem dims
#define GB     4
#define GN_SEQ 4096
#define GH     16
#define GD     64
#define GC     1024
#define GM     16384          // GB*GN_SEQ
#define GK     1024
#define GNO    3072           // 3*GC

// GEMM tiling
#define BM 128
#define BN 128
#define BKK 64                          // K elements per stage
#define STAGE_BYTES 49152               // Ahi 16K | Alo 16K | Bhi 16K
#define GEMM_SMEM (2 * STAGE_BYTES)     // 96 KB -> 2 CTAs/SM

// ---------------- scratch (static device globals; no allocation) -------------
__device__ __half g_Ah[(size_t)GM * GK];     // 32 MB x hi
__device__ __half g_Al[(size_t)GM * GK];     // 32 MB x lo
__device__ __half g_Wh[(size_t)GNO * GK];    //  6 MB w hi
__device__ float g_qkv[(size_t)GM * GNO];    // 192 MB qkv logits
__device__ float g_cpart[64 * 4 * 64 * 64];
__device__ float g_spart[64 * 4 * 64];
__device__ float g_ctx[64 * 64 * 64];

// ---------------- asm helpers ------------------------------------------------
#define LDSM4(r, addr)                                                         \
    asm volatile("ldmatrix.sync.aligned.m8n8.x4.shared.b16 {%0,%1,%2,%3},[%4];"\
                 : "=r"((r)[0]), "=r"((r)[1]), "=r"((r)[2]), "=r"((r)[3])      \
                 : "r"(addr))

#define MMA_F16(d, a, b0, b1)                                                  \
    asm volatile("mma.sync.aligned.m16n8k16.row.col.f32.f16.f16.f32 "          \
                 "{%0,%1,%2,%3},{%4,%5,%6,%7},{%8,%9},{%0,%1,%2,%3};"          \
                 : "+f"((d)[0]), "+f"((d)[1]), "+f"((d)[2]), "+f"((d)[3])      \
                 : "r"((a)[0]), "r"((a)[1]), "r"((a)[2]), "r"((a)[3]),         \
                   "r"(b0), "r"(b1))

#define CP_ASYNC16(dst, src)                                                   \
    asm volatile("cp.async.cg.shared.global [%0],[%1],16;" ::                  \
                 "r"(dst), "l"(src) : "memory")
#define CP_COMMIT() asm volatile("cp.async.commit_group;" ::: "memory")
#define CP_WAIT0()  asm volatile("cp.async.wait_group 0;" ::: "memory")

// ---------------- Kernel 0: fp32 -> fp16 split pre-pass ----------------------
// x -> (hi, lo) fp16 pair (exact Dekker-style split); w -> hi fp16 only.
__global__ __launch_bounds__(256) void split_kernel(const float* __restrict__ x,
                                                    const float* __restrict__ w)
{
    const size_t A4 = (size_t)GM * GK / 4;
    const size_t W4 = (size_t)GNO * GK / 4;
    const size_t total = A4 + W4;
    size_t stride = (size_t)gridDim.x * blockDim.x;
    for (size_t i = (size_t)blockIdx.x * blockDim.x + threadIdx.x; i < total; i += stride) {
        if (i < A4) {
            float4 v = ((const float4*)x)[i];
            __half h0 = __float2half_rn(v.x);
            __half h1 = __float2half_rn(v.y);
            __half h2 = __float2half_rn(v.z);
            __half h3 = __float2half_rn(v.w);
            __half l0 = __float2half_rn(v.x - __half2float(h0));
            __half l1 = __float2half_rn(v.y - __half2float(h1));
            __half l2 = __float2half_rn(v.z - __half2float(h2));
            __half l3 = __float2half_rn(v.w - __half2float(h3));
            ((__half2*)g_Ah)[i * 2]     = __halves2half2(h0, h1);
            ((__half2*)g_Ah)[i * 2 + 1] = __halves2half2(h2, h3);
            ((__half2*)g_Al)[i * 2]     = __halves2half2(l0, l1);
            ((__half2*)g_Al)[i * 2 + 1] = __halves2half2(l2, l3);
        } else {
            size_t j = i - A4;
            float4 v = ((const float4*)w)[j];
            ((__half2*)g_Wh)[j * 2]     = __halves2half2(__float2half_rn(v.x),
                                                         __float2half_rn(v.y));
            ((__half2*)g_Wh)[j * 2 + 1] = __halves2half2(__float2half_rn(v.z),
                                                         __float2half_rn(v.w));
        }
    }
}

// ---------------- stage loader ------------------------------------------------
// Stage layout: [Ahi 128x128B | Alo 128x128B | Bhi 128x128B]; within each
// region: row*128B, 16B chunk c stored at (c ^ (row&7))*16  (SW128 pattern).
__device__ __forceinline__ void issue_stage(int kt, int bm, int bn,
                                            unsigned sbase, int t)
{
    const int k0 = kt * BKK;
    const unsigned buf = sbase + (kt & 1) * STAGE_BYTES;
#pragma unroll
    for (int i = 0; i < 4; ++i) {
        int idx = t + i * 256;          // 0..1023
        int row = idx >> 3;
        int c   = idx & 7;
        unsigned soff = (unsigned)(row * 128 + ((c ^ (row & 7)) << 4));
        const __half* ga = g_Ah + (size_t)(bm + row) * GK + k0 + c * 8;
        CP_ASYNC16(buf + soff, ga);
        const __half* gl = g_Al + (size_t)(bm + row) * GK + k0 + c * 8;
        CP_ASYNC16(buf + 16384 + soff, gl);
        const __half* gb = g_Wh + (size_t)(bn + row) * GK + k0 + c * 8;
        CP_ASYNC16(buf + 32768 + soff, gb);
    }
}

// ---------------- Kernel 1: QKV GEMM (fp16 hi/lo 2-MMA, occ 2) --------------
__global__ __launch_bounds__(256, 2) void qkv_gemm_f16()
{
    extern __shared__ char smraw[];
    const unsigned sbase = (unsigned)__cvta_generic_to_shared(smraw);

    const int t    = threadIdx.x;
    const int bn   = blockIdx.x * BN;     // N fastest: W hot in L2
    const int bm   = blockIdx.y * BM;
    const int lane = t & 31;
    const int warp = t >> 5;
    const int wm   = warp >> 2;           // 0..1 (64-row warp tiles)
    const int wn   = warp & 3;            // 0..3 (32-col warp tiles)

    // per-lane ldmatrix offsets per k16 group g: chunks 2g, 2g+1
    const int lr = lane & 15;
    const int ls = lane >> 4;
    unsigned off[4];
#pragma unroll
    for (int g = 0; g < 4; ++g)
        off[g] = (unsigned)(lr * 128 + (((2 * g) + ls) ^ (lr & 7)) * 16);

    float acc[4][4][4];
#pragma unroll
    for (int i = 0; i < 4; ++i)
#pragma unroll
        for (int j = 0; j < 4; ++j)
#pragma unroll
            for (int c = 0; c < 4; ++c) acc[i][j][c] = 0.0f;

    issue_stage(0, bm, bn, sbase, t);
    CP_COMMIT();

    const int NT = GK / BKK;   // 16
    for (int kt = 0; kt < NT; ++kt) {
        CP_WAIT0();            // stage kt resident (only pending group)
        __syncthreads();       // also: all warps done computing stage kt-1
        if (kt + 1 < NT) {
            issue_stage(kt + 1, bm, bn, sbase, t);   // overlaps compute kt
            CP_COMMIT();
        }

        const unsigned slot = sbase + (kt & 1) * STAGE_BYTES;
        const unsigned aHi  = slot +         (wm * 64) * 128;
        const unsigned aLo  = slot + 16384 + (wm * 64) * 128;
        const unsigned bBs  = slot + 32768 + (wn * 32) * 128;

#pragma unroll
        for (int ks = 0; ks < 4; ++ks) {
            unsigned ah[4][4], al[4][4], bb[2][4];
#pragma unroll
            for (int mt = 0; mt < 4; ++mt) {
                LDSM4(ah[mt], aHi + mt * 2048 + off[ks]);
                LDSM4(al[mt], aLo + mt * 2048 + off[ks]);
            }
#pragma unroll
            for (int p = 0; p < 2; ++p)
                LDSM4(bb[p], bBs + p * 2048 + off[ks]);
#pragma unroll
            for (int mt = 0; mt < 4; ++mt)
#pragma unroll
                for (int p = 0; p < 2; ++p)
#pragma unroll
                    for (int j = 0; j < 2; ++j) {
                        const int nt = p * 2 + j;
                        MMA_F16(acc[mt][nt], ah[mt], bb[p][j], bb[p][j + 2]);
                        MMA_F16(acc[mt][nt], al[mt], bb[p][j], bb[p][j + 2]);
                    }
        }
    }

    // epilogue
    const int g  = lane >> 2;
    const int tc = lane & 3;
#pragma unroll
    for (int mt = 0; mt < 4; ++mt)
#pragma unroll
        for (int nt = 0; nt < 4; ++nt) {
            int row = bm + wm * 64 + mt * 16 + g;
            int col = bn + wn * 32 + nt * 8 + tc * 2;
            *(float2*)(g_qkv + (size_t)row * GNO + col) =
                make_float2(acc[mt][nt][0], acc[mt][nt][1]);
            *(float2*)(g_qkv + (size_t)(row + 8) * GNO + col) =
                make_float2(acc[mt][nt][2], acc[mt][nt][3]);
        }
}

// ---------------- Kernel 2: per-(bh,chunk) partial context + k-exp sums ------
__global__ __launch_bounds__(512) void ctx_partial_kernel()
{
    const int bh    = blockIdx.x;
    const int chunk = blockIdx.y;
    const int b = bh >> 4, h = bh & 15;

    __shared__ __align__(16) float sk[32][64];
    __shared__ __align__(16) float sv[32][64];
    __shared__ __align__(16) float ps[32][64];

    const int t  = threadIdx.x;
    const int li = t >> 4;
    const int lc = t & 15;
    const int dg = t >> 4;
    const int eg = t & 15;

    float acc[2][4] = {{0, 0, 0, 0}, {0, 0, 0, 0}};
    float sacc[4] = {0, 0, 0, 0};

    const float* kbase = g_qkv + ((size_t)b * GN_SEQ) * GNO + 1024 + h * 64;

    for (int tile = 0; tile < 32; ++tile) {
        const int n = chunk * 1024 + tile * 32 + li;
        const float* kr = kbase + (size_t)n * GNO;
        float4 kk = *(const float4*)(kr + lc * 4);
        float4 vv = *(const float4*)(kr + 1024 + lc * 4);
        float4 ek;
        ek.x = __expf(kk.x); ek.y = __expf(kk.y);
        ek.z = __expf(kk.z); ek.w = __expf(kk.w);
        sacc[0] += ek.x; sacc[1] += ek.y; sacc[2] += ek.z; sacc[3] += ek.w;
        ((float4*)sk[li])[lc] = ek;
        ((float4*)sv[li])[lc] = vv;
        __syncthreads();
#pragma unroll 4
        for (int nn = 0; nn < 32; ++nn) {
            float a0 = sk[nn][dg * 2];
            float a1 = sk[nn][dg * 2 + 1];
            float4 v4 = ((float4*)sv[nn])[eg];
            acc[0][0] += a0 * v4.x; acc[0][1] += a0 * v4.y;
            acc[0][2] += a0 * v4.z; acc[0][3] += a0 * v4.w;
            acc[1][0] += a1 * v4.x; acc[1][1] += a1 * v4.y;
            acc[1][2] += a1 * v4.z; acc[1][3] += a1 * v4.w;
        }
        __syncthreads();
    }

    const size_t cbase = ((size_t)(bh * 4 + chunk)) * 4096;
#pragma unroll
    for (int i = 0; i < 2; ++i) {
        int d = dg * 2 + i;
        ((float4*)(g_cpart + cbase + d * 64))[eg] =
            make_float4(acc[i][0], acc[i][1], acc[i][2], acc[i][3]);
    }

    ((float4*)ps[li])[lc] = make_float4(sacc[0], sacc[1], sacc[2], sacc[3]);
    __syncthreads();
    if (t < 64) {
        float s = 0.0f;
#pragma unroll
        for (int i = 0; i < 32; ++i) s += ps[i][t];
        g_spart[(bh * 4 + chunk) * 64 + t] = s;
    }
}

// ---------------- Kernel 3: reduce chunks + normalize context ---------------
__global__ __launch_bounds__(256) void ctx_reduce_kernel()
{
    const int bh = blockIdx.x;
    const int t  = threadIdx.x;
    __shared__ float sinvS[64];
    if (t < 64) {
        const float* sp = g_spart + (size_t)bh * 256 + t;
        float s = sp[0] + sp[64] + sp[128] + sp[192];
        sinvS[t] = 1.0f / s;
    }
    __syncthreads();
    const float* cp = g_cpart + (size_t)bh * 16384;
    for (int idx = t; idx < 4096; idx += 256) {
        float c = cp[idx] + cp[idx + 4096] + cp[idx + 8192] + cp[idx + 12288];
        g_ctx[(size_t)bh * 4096 + idx] = c * sinvS[idx >> 6];
    }
}

// ---------------- Kernel 4: q-softmax (over d) + out = q_soft @ ctx ---------
__global__ __launch_bounds__(256) void out_kernel_f(float* __restrict__ out)
{
    const int nb = blockIdx.x;
    const int bh = blockIdx.y;
    const int b = bh >> 4, h = bh & 15;

    __shared__ __align__(16) float sctx[64][64];
    __shared__ __align__(16) float sq[64][68];
    __shared__ float prow[64][4];
    __shared__ float sinv[64];

    const int t = threadIdx.x;

    const float4* cg = (const float4*)(g_ctx + (size_t)bh * 4096);
    float4* cs = (float4*)sctx;
#pragma unroll
    for (int j = 0; j < 4; ++j) cs[t + 256 * j] = cg[t + 256 * j];

    const int r  = t >> 2;
    const int qp = t & 3;
    const float* qrow = g_qkv + ((size_t)(b * GN_SEQ + nb * 64 + r)) * GNO + h * 64;
    float psum = 0.0f;
#pragma unroll
    for (int c4 = 0; c4 < 4; ++c4) {
        int d0 = qp * 16 + c4 * 4;
        float4 qv = *(const float4*)(qrow + d0);
        float e0 = __expf(qv.x), e1 = __expf(qv.y), e2 = __expf(qv.z), e3 = __expf(qv.w);
        sq[r][d0] = e0; sq[r][d0 + 1] = e1; sq[r][d0 + 2] = e2; sq[r][d0 + 3] = e3;
        psum += e0 + e1 + e2 + e3;
    }
    prow[r][qp] = psum;
    __syncthreads();
    if (t < 64)
        sinv[t] = 0.125f / (prow[t][0] + prow[t][1] + prow[t][2] + prow[t][3]);
    __syncthreads();

    {
        float myinv = sinv[r];
#pragma unroll
        for (int c4 = 0; c4 < 4; ++c4) {
            int d0 = qp * 16 + c4 * 4;
            sq[r][d0] *= myinv; sq[r][d0 + 1] *= myinv;
            sq[r][d0 + 2] *= myinv; sq[r][d0 + 3] *= myinv;
        }
    }
    __syncthreads();

    const int rg  = t >> 4;
    const int egx = t & 15;
    float acc[4][4] = {{0}};
#pragma unroll 4
    for (int d = 0; d < 64; ++d) {
        float4 c4v = ((float4*)sctx[d])[egx];
#pragma unroll
        for (int i = 0; i < 4; ++i) {
            float qv = sq[rg * 4 + i][d];
            acc[i][0] += qv * c4v.x; acc[i][1] += qv * c4v.y;
            acc[i][2] += qv * c4v.z; acc[i][3] += qv * c4v.w;
        }
    }
#pragma unroll
    for (int i = 0; i < 4; ++i) {
        int n = nb * 64 + rg * 4 + i;
        ((float4*)(out + ((size_t)bh * GN_SEQ + n) * 64))[egx] =
            make_float4(acc[i][0], acc[i][1], acc[i][2], acc[i][3]);
    }
}

// ---------------- launcher ----------------------------------------------------
extern "C" void kernel_launch(void* const* d_in, const int* in_sizes, int n_in,
                              void* d_out, int out_size)
{
    const float* x = (const float*)d_in[0];     // [4,4096,1024]
    const float* w = (const float*)d_in[1];     // [3072,1024]
    float* out = (float*)d_out;                 // [4,16,4096,64]

    cudaFuncSetAttribute(qkv_gemm_f16,
                         cudaFuncAttributeMaxDynamicSharedMemorySize, GEMM_SMEM);

    split_kernel<<<4096, 256>>>(x, w);

    dim3 gGemm(GNO / BN, GM / BM);              // (24, 128) — N fastest for L2 reuse
    qkv_gemm_f16<<<gGemm, 256, GEMM_SMEM>>>();

    dim3 gCtx(64, 4);
    ctx_partial_kernel<<<gCtx, 512>>>();

    ctx_reduce_kernel<<<64, 256>>>();

    dim3 gOut(64, 64);
    out_kernel_f<<<gOut, 256>>>(out);
}